// round 9
// baseline (speedup 1.0000x reference)
#include <cuda_runtime.h>
#include <math.h>

#define TSTEPS  2048
#define FDIM    15
#define NGROUPS 8
#define BG      8      // batch rows per group
#define CS      16     // cluster size = slices per group
#define NT      384
#define NCTA    128
#define SP      260    // padded row stride for h state (floats)
#define WS      260    // padded row stride for weights (floats)
#define HBUF    (8 * SP)          // 2080 floats: one h buffer (8 rows)
#define SHH_F   (144 * WS)        // float offset of h buffers within smem
#define RB      148    // red row stride
#define RKC     (8 * RB)          // red kc stride = 1184

typedef unsigned long long u64;

__device__ __forceinline__ float sigmoidf_(float x) {
    return __fdividef(1.0f, 1.0f + __expf(-x));
}

// packed f32x2 fma
__device__ __forceinline__ u64 ffma2(u64 a, u64 b, u64 c) {
    u64 d;
    asm("fma.rn.f32x2 %0, %1, %2, %3;" : "=l"(d) : "l"(a), "l"(b), "l"(c));
    return d;
}

__device__ __forceinline__ unsigned mapa_u32(unsigned addr, unsigned rank) {
    unsigned r;
    asm("mapa.shared::cluster.u32 %0, %1, %2;" : "=r"(r) : "r"(addr), "r"(rank));
    return r;
}
__device__ __forceinline__ void st_cluster_f32(unsigned addr, float v) {
    asm volatile("st.shared::cluster.f32 [%0], %1;" :: "r"(addr), "f"(v));
}
__device__ __forceinline__ void cluster_sync_() {
    asm volatile("barrier.cluster.arrive.aligned;" ::: "memory");
    asm volatile("barrier.cluster.wait.aligned;" ::: "memory");
}

__global__ void __launch_bounds__(NT, 1)
gru_kernel(const float* __restrict__ inp, const float* __restrict__ W1,
           const float* __restrict__ U1g, const float* __restrict__ b1,
           const float* __restrict__ W2g, const float* __restrict__ U2g,
           const float* __restrict__ b2, float* __restrict__ out)
{
    extern __shared__ float smem[];
    float* sW   = smem;                 // [144][WS]: 0..47 U1, 48..95 W2, 96..143 U2 (transposed)
    float* shh  = sW   + 144 * WS;      // 4 x HBUF: h1[p0], h1[p1], h2[p0], h2[p1]
    float* sW1t = shh  + 4 * HBUF;      // [48][16]
    float* sx   = sW1t + 48 * 16;       // [8][16]
    float* sb   = sx   + 8 * 16;        // [4*48]: b1_in | b1_rec | b2_in | b2_rec
    float* red  = sb   + 4 * 48;        // [8 kc][8 rows * RB]

    const int tid   = threadIdx.x;
    const int grp   = blockIdx.x >> 4;
    const int sl    = blockIdx.x & 15;
    const int brow0 = grp * BG;

    // ---- one-time: load weight slices (transposed) into SMEM ----
    for (int idx = tid; idx < 48 * 256; idx += NT) {
        int k = idx / 48, c = idx - k * 48;
        int col = ((c >> 4) << 8) + (sl << 4) + (c & 15);   // gate*256 + slice*16 + u
        sW[c * WS + k]          = U1g[k * 768 + col];
        sW[(48 + c) * WS + k]   = W2g[k * 768 + col];
        sW[(96 + c) * WS + k]   = U2g[k * 768 + col];
    }
    for (int idx = tid; idx < 48 * 15; idx += NT) {
        int f = idx / 48, c = idx - f * 48;
        int col = ((c >> 4) << 8) + (sl << 4) + (c & 15);
        sW1t[c * 16 + f] = W1[f * 768 + col];
    }
    for (int c = tid; c < 48; c += NT) {
        int col = ((c >> 4) << 8) + (sl << 4) + (c & 15);
        sb[c]        = b1[col];        // b1_in
        sb[48 + c]   = b1[768 + col];  // b1_rec
        sb[96 + c]   = b2[col];        // b2_in
        sb[144 + c]  = b2[768 + col];  // b2_rec
    }
    // zero all 4 h buffers (both parities of both layers)
    for (int idx = tid; idx < 4 * HBUF; idx += NT) shh[idx] = 0.f;

    // smem base address (u32 shared window) + per-rank mapa bases
    unsigned sbase;
    asm("{ .reg .u64 t; cvta.to.shared.u64 t, %1; cvt.u32.u64 %0, t; }"
        : "=r"(sbase) : "l"(smem));
    unsigned rbase[CS];
    #pragma unroll
    for (int r = 0; r < CS; r++) rbase[r] = mapa_u32(sbase, (unsigned)r);

    // thread tile decomposition: kc (k-chunk of 32) x cg (6 cols) x rh (4 rows)
    const int kc  = tid / 48;          // 0..7
    const int r48 = tid - kc * 48;
    const int cg  = r48 >> 1;          // 0..23 (cols cg*6 .. cg*6+5; cg<16 -> h1, else h2)
    const int rh  = r48 & 1;           // 0..1
    const float* wbase = sW + (cg * 6) * WS + kc * 32;
    const int hoff = rh * 4 * SP + kc * 32;

    const int b15 = tid / 15, f15 = tid - b15 * 15;   // input-load map (tid<120)

    cluster_sync_();   // weights + zeroed state visible cluster-wide

    for (int i = 0; i <= TSTEPS; ++i) {
        const int p = i & 1, q = p ^ 1;
        const float* h1b = shh + p * HBUF;         // h1[i-1]
        const float* h2b = shh + (2 + p) * HBUF;   // h2[i-2]

        // prefetch input row i (latency hidden behind GEMM)
        float xin = 0.f;
        if (i < TSTEPS && tid < 120)
            xin = __ldg(&inp[(size_t)(brow0 + b15) * (TSTEPS * FDIM) + i * FDIM + f15]);

        // ---- fused register-tiled GEMM: [rec1 | xp2 | rec2] = [h1|h1|h2] @ [U1|W2|U2] ----
        {
            const float* hsel = (cg < 16 ? h1b : h2b) + hoff;
            u64 acc[4][6];
            #pragma unroll
            for (int j = 0; j < 4; j++)
                #pragma unroll
                for (int jj = 0; jj < 6; jj++) acc[j][jj] = 0ull;

            #pragma unroll
            for (int s = 0; s < 8; s++) {
                ulonglong2 h2v[4];
                #pragma unroll
                for (int j = 0; j < 4; j++)
                    h2v[j] = *(const ulonglong2*)(hsel + j * SP + s * 4);
                #pragma unroll
                for (int jj = 0; jj < 6; jj++) {
                    ulonglong2 w2 = *(const ulonglong2*)(wbase + jj * WS + s * 4);
                    #pragma unroll
                    for (int j = 0; j < 4; j++) {
                        acc[j][jj] = ffma2(h2v[j].x, w2.x, acc[j][jj]);
                        acc[j][jj] = ffma2(h2v[j].y, w2.y, acc[j][jj]);
                    }
                }
            }
            #pragma unroll
            for (int j = 0; j < 4; j++) {
                int row = rh * 4 + j;
                #pragma unroll
                for (int jj = 0; jj < 6; jj += 2) {
                    float2 p0 = *(float2*)&acc[j][jj];
                    float2 p1 = *(float2*)&acc[j][jj + 1];
                    *(float2*)&red[kc * RKC + row * RB + cg * 6 + jj] =
                        make_float2(p0.x + p0.y, p1.x + p1.y);
                }
            }
        }
        if (i < TSTEPS && tid < 120) sx[b15 * 16 + f15] = xin;
        __syncthreads();

        // ---- gates + state update + DSMEM broadcast (128 threads: one (b,u)) ----
        if (tid < 128) {
            int b = tid & 7, u = tid >> 3;
            int scol = (sl << 4) + u;
            int gb = brow0 + b;
            const float* rrow = red + b * RB;
            float hn1 = 0.f, hn2 = 0.f;

            if (i < TSTEPS) {   // layer 1: h1[i]
                float rec[3], xp[3];
                #pragma unroll
                for (int g = 0; g < 3; g++) {
                    int c = g * 16 + u;
                    float s = rrow[c];
                    #pragma unroll
                    for (int k2 = 1; k2 < 8; k2++) s += rrow[k2 * RKC + c];
                    rec[g] = s + sb[48 + c];                 // + b1_rec
                    float a = sb[c];                         // b1_in
                    const float* wr = sW1t + c * 16;
                    const float* xr = sx + b * 16;
                    #pragma unroll
                    for (int f = 0; f < 15; f++) a += xr[f] * wr[f];
                    xp[g] = a;
                }
                float z  = sigmoidf_(xp[0] + rec[0]);
                float r  = sigmoidf_(xp[1] + rec[1]);
                float hh = fmaxf(0.f, xp[2] + r * rec[2]);
                float hp = h1b[b * SP + scol];
                hn1 = z * hp + (1.f - z) * hh;
                if (i == TSTEPS - 1) out[64 * 256 + gb * 256 + scol] = hn1;  // state1
            }
            if (i >= 1) {       // layer 2: h2[i-1]
                float xpv[3], rec[3];
                #pragma unroll
                for (int g = 0; g < 3; g++) {
                    int cx = 48 + g * 16 + u;
                    int cr = 96 + g * 16 + u;
                    float sx_ = rrow[cx];
                    float sr_ = rrow[cr];
                    #pragma unroll
                    for (int k2 = 1; k2 < 8; k2++) {
                        sx_ += rrow[k2 * RKC + cx];
                        sr_ += rrow[k2 * RKC + cr];
                    }
                    xpv[g] = sx_ + sb[96 + g * 16 + u];   // + b2_in
                    rec[g] = sr_ + sb[144 + g * 16 + u];  // + b2_rec
                }
                float z  = sigmoidf_(xpv[0] + rec[0]);
                float r  = sigmoidf_(xpv[1] + rec[1]);
                float hh = fmaxf(0.f, xpv[2] + r * rec[2]);
                float hp = h2b[b * SP + scol];
                hn2 = z * hp + (1.f - z) * hh;
                if (i == TSTEPS) {
                    out[gb * 256 + scol]                = hn2;   // x = seq2[:, -1, :]
                    out[2 * 64 * 256 + gb * 256 + scol] = hn2;   // state2
                }
            }

            // broadcast new state into parity-q buffers of all 16 cluster CTAs
            unsigned off1 = 4u * (unsigned)(SHH_F + q * HBUF + b * SP + scol);
            unsigned off2 = off1 + 4u * (2u * HBUF);
            bool w1 = (i < TSTEPS);
            bool w2 = (i >= 1) && (i < TSTEPS);
            #pragma unroll
            for (int r = 0; r < CS; r++) {
                if (w1) st_cluster_f32(rbase[r] + off1, hn1);
                if (w2) st_cluster_f32(rbase[r] + off2, hn2);
            }
        }

        cluster_sync_();
    }
}

extern "C" void kernel_launch(void* const* d_in, const int* in_sizes, int n_in,
                              void* d_out, int out_size) {
    const float* inp = (const float*)d_in[0];
    const float* W1  = (const float*)d_in[1];
    const float* U1  = (const float*)d_in[2];
    const float* b1  = (const float*)d_in[3];
    const float* W2  = (const float*)d_in[4];
    const float* U2  = (const float*)d_in[5];
    const float* b2  = (const float*)d_in[6];
    float* out = (float*)d_out;

    size_t smem_bytes = (size_t)(144 * WS + 4 * HBUF +
                                 48 * 16 + 8 * 16 + 4 * 48 +
                                 8 * RKC) * sizeof(float);

    cudaFuncSetAttribute(gru_kernel, cudaFuncAttributeMaxDynamicSharedMemorySize,
                         (int)smem_bytes);
    cudaFuncSetAttribute(gru_kernel, cudaFuncAttributeNonPortableClusterSizeAllowed, 1);

    cudaLaunchConfig_t cfg = {};
    cfg.gridDim  = dim3(NCTA, 1, 1);
    cfg.blockDim = dim3(NT, 1, 1);
    cfg.dynamicSmemBytes = smem_bytes;
    cfg.stream = 0;
    cudaLaunchAttribute attrs[1];
    attrs[0].id = cudaLaunchAttributeClusterDimension;
    attrs[0].val.clusterDim.x = CS;
    attrs[0].val.clusterDim.y = 1;
    attrs[0].val.clusterDim.z = 1;
    cfg.attrs = attrs;
    cfg.numAttrs = 1;

    cudaLaunchKernelEx(&cfg, gru_kernel, inp, W1, U1, b1, W2, U2, b2, out);
}

// round 11
// speedup vs baseline: 1.4831x; 1.4831x over previous
#include <cuda_runtime.h>
#include <math.h>

#define TSTEPS  2048
#define FDIM    15
#define NGROUPS 8
#define BG      8      // batch rows per group
#define NT      384
#define NCTA    128
#define SPH     260    // padded row stride for h state (floats), 16B-aligned rows
#define WS      260    // padded row stride for weights (floats), 16B-aligned rows
#define RB      148    // red row stride
#define RKC     1188   // red kc stride = 8*RB + 4

typedef unsigned long long u64;

// Double-buffered hidden states (tiny: live in L2)
__device__ float    g_h1[2 * NGROUPS * BG * 256];
__device__ float    g_h2[2 * NGROUPS * BG * 256];
__device__ unsigned g_flags[NCTA];

__global__ void init_kernel() {
    if (threadIdx.x < NCTA) g_flags[threadIdx.x] = 0u;
}

__device__ __forceinline__ float sigmoidf_(float x) {
    return __fdividef(1.0f, 1.0f + __expf(-x));
}

// packed f32x2 fma
__device__ __forceinline__ u64 ffma2(u64 a, u64 b, u64 c) {
    u64 d;
    asm("fma.rn.f32x2 %0, %1, %2, %3;" : "=l"(d) : "l"(a), "l"(b), "l"(c));
    return d;
}

// arrive: block sync, then tid0 fences + publishes epoch to its own flag
__device__ __forceinline__ void bar_arrive(unsigned cta, unsigned e) {
    __syncthreads();
    if (threadIdx.x == 0) {
        __threadfence();
        atomicExch(&g_flags[cta], e);
    }
}
// wait: warp 0 polls all 16 flags of the group (one 64B sector), broadcast via bar
__device__ __forceinline__ void bar_wait(int grp, unsigned e) {
    if (threadIdx.x < 32) {
        int lane = threadIdx.x;
        for (;;) {
            unsigned v = e;
            if (lane < 16) v = ((volatile unsigned*)g_flags)[grp * 16 + lane];
            if (__all_sync(0xffffffffu, v >= e)) break;
        }
        if (lane == 0) __threadfence();
    }
    __syncthreads();
}

__global__ void __launch_bounds__(NT, 1)
gru_kernel(const float* __restrict__ inp, const float* __restrict__ W1,
           const float* __restrict__ U1g, const float* __restrict__ b1,
           const float* __restrict__ W2g, const float* __restrict__ U2g,
           const float* __restrict__ b2, float* __restrict__ out)
{
    extern __shared__ float smem[];
    float* sW    = smem;                  // [144][WS]: 0..47 U1, 48..95 W2, 96..143 U2 (transposed)
    float* sh1   = sW    + 144 * WS;      // [8][SPH]  h1[i-1]
    float* sh2   = sh1   +   8 * SPH;     // [8][SPH]  h2[i-2]
    float* sW1t  = sh2   +   8 * SPH;     // [48][16]
    float* sx    = sW1t  +  48 * 16;      // [8][16]
    float* sb    = sx    +   8 * 16;      // [4*48]: b1_in | b1_rec | b2_in | b2_rec
    float* sxp   = sb    +   4 * 48;      // [3][128]  xp1 per (b,u)
    float* sacc1 = sxp   +   3 * 128;     // [8][96]
    float* sacc2 = sacc1 +   8 * 96;      // [8][48]
    float* red   = sacc2 +   8 * 48;      // [8 kc][8 rows * RB]

    const int tid   = threadIdx.x;
    const int cta   = blockIdx.x;
    const int grp   = cta >> 4;
    const int sl    = cta & 15;
    const int brow0 = grp * BG;

    // ---- one-time: load weight slices (transposed) into SMEM ----
    for (int idx = tid; idx < 48 * 256; idx += NT) {
        int k = idx / 48, c = idx - k * 48;
        int col = ((c >> 4) << 8) + (sl << 4) + (c & 15);   // gate*256 + slice*16 + u
        sW[c * WS + k]          = U1g[k * 768 + col];
        sW[(48 + c) * WS + k]   = W2g[k * 768 + col];
        sW[(96 + c) * WS + k]   = U2g[k * 768 + col];
    }
    for (int idx = tid; idx < 48 * 15; idx += NT) {
        int f = idx / 48, c = idx - f * 48;
        int col = ((c >> 4) << 8) + (sl << 4) + (c & 15);
        sW1t[c * 16 + f] = W1[f * 768 + col];
    }
    for (int c = tid; c < 48; c += NT) {
        int col = ((c >> 4) << 8) + (sl << 4) + (c & 15);
        sb[c]        = b1[col];        // b1_in
        sb[48 + c]   = b1[768 + col];  // b1_rec
        sb[96 + c]   = b2[col];        // b2_in
        sb[144 + c]  = b2[768 + col];  // b2_rec
    }
    if (tid < 128) {
        int b = tid & 7, u = tid >> 3;
        int scol = (sl << 4) + u;
        for (int buf = 0; buf < 2; buf++) {
            g_h1[(buf * NGROUPS + grp) * BG * 256 + b * 256 + scol] = 0.f;
            g_h2[(buf * NGROUPS + grp) * BG * 256 + b * 256 + scol] = 0.f;
        }
    }

    // GEMM decomposition (tid < 192): kc (k-chunk of 32) x cg (6 cols), 8 rows each
    const int kc = tid / 24;           // 0..7
    const int cg = tid - kc * 24;      // 0..23 (cols cg*6..cg*6+5; cg<16 -> h1, else h2)
    const float* hsel = (cg < 16 ? sh1 : sh2) + kc * 32;
    const float* wbse = sW + (cg * 6) * WS + kc * 32;

    const int b15 = tid / 15, f15 = tid - b15 * 15;   // input-load map (tid<120)

    // registers carrying this thread's own state element (tid<128 only meaningful)
    float hp1 = 0.f, hp2 = 0.f;

    bar_arrive(cta, 1u);
    bar_wait(grp, 1u);

    for (int i = 0; i <= TSTEPS; ++i) {
        // ---- prefetch input row i (independent of barrier) ----
        float xin = 0.f;
        if (i < TSTEPS && tid < 120)
            xin = __ldg(&inp[(size_t)(brow0 + b15) * (TSTEPS * FDIM) + i * FDIM + f15]);

        if (i > 0) bar_wait(grp, (unsigned)(i + 1));

        // ---- phase 1: load shared state (L2-coherent) ----
        {
            const float* gh1 = g_h1 + (((i + 1) & 1) * NGROUPS + grp) * BG * 256;  // h1[i-1]
            const float* gh2 = g_h2 + (((i) & 1)     * NGROUPS + grp) * BG * 256;  // h2[i-2]
            for (int idx = tid; idx < 512; idx += NT) {
                int b = idx >> 6, k4 = idx & 63;
                float4 v1 = __ldcg(((const float4*)(gh1 + b * 256)) + k4);
                float4 v2 = __ldcg(((const float4*)(gh2 + b * 256)) + k4);
                *(float4*)(sh1 + b * SPH + (k4 << 2)) = v1;
                *(float4*)(sh2 + b * SPH + (k4 << 2)) = v2;
            }
            if (i < TSTEPS && tid < 120) sx[b15 * 16 + f15] = xin;
        }
        __syncthreads();

        // ---- phase 2: GEMM (192 thr) + x-projection helpers (128 thr) ----
        if (tid < 192) {
            u64 acc[8][6];
            #pragma unroll
            for (int j = 0; j < 8; j++)
                #pragma unroll
                for (int jj = 0; jj < 6; jj++) acc[j][jj] = 0ull;

            #pragma unroll
            for (int s = 0; s < 8; s++) {
                ulonglong2 w2[6];
                #pragma unroll
                for (int jj = 0; jj < 6; jj++)
                    w2[jj] = *(const ulonglong2*)(wbse + jj * WS + s * 4);
                #pragma unroll
                for (int j = 0; j < 8; j++) {
                    ulonglong2 hv = *(const ulonglong2*)(hsel + j * SPH + s * 4);
                    #pragma unroll
                    for (int jj = 0; jj < 6; jj++) {
                        acc[j][jj] = ffma2(hv.x, w2[jj].x, acc[j][jj]);
                        acc[j][jj] = ffma2(hv.y, w2[jj].y, acc[j][jj]);
                    }
                }
            }
            #pragma unroll
            for (int j = 0; j < 8; j++) {
                #pragma unroll
                for (int jj = 0; jj < 6; jj += 2) {
                    float2 p0 = *(float2*)&acc[j][jj];
                    float2 p1 = *(float2*)&acc[j][jj + 1];
                    *(float2*)&red[kc * RKC + j * RB + cg * 6 + jj] =
                        make_float2(p0.x + p0.y, p1.x + p1.y);
                }
            }
        } else if (tid < 320) {
            int bu = tid - 192;
            int b = bu & 7, u = bu >> 3;
            #pragma unroll
            for (int g = 0; g < 3; g++) {
                int c = g * 16 + u;
                float a = sb[c];                       // b1_in
                const float* wr = sW1t + c * 16;
                const float* xr = sx + b * 16;
                #pragma unroll
                for (int f = 0; f < 15; f++) a += xr[f] * wr[f];
                sxp[g * 128 + bu] = a;
            }
        }
        __syncthreads();

        // ---- phase 2c: reduce over kc (3 outputs per thread) ----
        #pragma unroll
        for (int t = 0; t < 3; t++) {
            int o = tid * 3 + t;
            int row = o / 144, col = o - row * 144;
            const float* rp = red + row * RB + col;
            float s = rp[0];
            #pragma unroll
            for (int k2 = 1; k2 < 8; k2++) s += rp[k2 * RKC];
            if (col < 96) sacc1[row * 96 + col] = s;
            else          sacc2[row * 48 + (col - 96)] = s;
        }
        __syncthreads();

        // ---- phase 3: gates + state update (128 threads: one (b,u) each) ----
        if (tid < 128) {
            int b = tid & 7, u = tid >> 3;
            int scol = (sl << 4) + u;
            int gb = brow0 + b;

            if (i < TSTEPS) {   // layer 1: h1[i]
                float rec[3];
                #pragma unroll
                for (int g = 0; g < 3; g++)
                    rec[g] = sacc1[b * 96 + g * 16 + u] + sb[48 + g * 16 + u];  // + b1_rec
                float z  = sigmoidf_(sxp[tid]           + rec[0]);
                float r  = sigmoidf_(sxp[128 + tid]     + rec[1]);
                float hh = fmaxf(0.f, sxp[256 + tid] + r * rec[2]);
                float hn = z * hp1 + (1.f - z) * hh;
                hp1 = hn;
                g_h1[((i & 1) * NGROUPS + grp) * BG * 256 + b * 256 + scol] = hn;
                if (i == TSTEPS - 1) out[64 * 256 + gb * 256 + scol] = hn;   // state1
            }
            if (i >= 1) {       // layer 2: h2[i-1]
                float xpv[3], rec[3];
                #pragma unroll
                for (int g = 0; g < 3; g++) {
                    xpv[g] = sacc1[b * 96 + 48 + g * 16 + u] + sb[96 + g * 16 + u];   // + b2_in
                    rec[g] = sacc2[b * 48 + g * 16 + u]      + sb[144 + g * 16 + u];  // + b2_rec
                }
                float z  = sigmoidf_(xpv[0] + rec[0]);
                float r  = sigmoidf_(xpv[1] + rec[1]);
                float hh = fmaxf(0.f, xpv[2] + r * rec[2]);
                float hn = z * hp2 + (1.f - z) * hh;
                hp2 = hn;
                g_h2[(((i - 1) & 1) * NGROUPS + grp) * BG * 256 + b * 256 + scol] = hn;
                if (i == TSTEPS) {
                    out[gb * 256 + scol]                = hn;   // x = seq2[:, -1, :]
                    out[2 * 64 * 256 + gb * 256 + scol] = hn;   // state2
                }
            }
        }

        bar_arrive(cta, (unsigned)(i + 2));
    }
}

extern "C" void kernel_launch(void* const* d_in, const int* in_sizes, int n_in,
                              void* d_out, int out_size) {
    const float* inp = (const float*)d_in[0];
    const float* W1  = (const float*)d_in[1];
    const float* U1  = (const float*)d_in[2];
    const float* b1  = (const float*)d_in[3];
    const float* W2  = (const float*)d_in[4];
    const float* U2  = (const float*)d_in[5];
    const float* b2  = (const float*)d_in[6];
    float* out = (float*)d_out;

    size_t smem_bytes = (size_t)(144 * WS + 2 * 8 * SPH +
                                 48 * 16 + 8 * 16 + 4 * 48 + 3 * 128 +
                                 8 * 96 + 8 * 48 + 8 * RKC) * sizeof(float);
    cudaFuncSetAttribute(gru_kernel, cudaFuncAttributeMaxDynamicSharedMemorySize,
                         (int)smem_bytes);
    init_kernel<<<1, 128>>>();
    gru_kernel<<<NCTA, NT, smem_bytes>>>(inp, W1, U1, b1, W2, U2, b2, out);
}

// round 12
// speedup vs baseline: 1.8673x; 1.2590x over previous
#include <cuda_runtime.h>
#include <math.h>

#define TSTEPS  2048
#define FDIM    15
#define NGROUPS 8
#define BG      8      // batch rows per group
#define NT      384
#define NCTA    128
#define SPH     260    // padded row stride for h state (floats), 16B-aligned rows
#define WS      260    // padded row stride for weights (floats), 16B-aligned rows
#define RB      148    // red row stride
#define RKC     1188   // red kc stride = 8*RB + 4

typedef unsigned long long u64;

// Double-buffered hidden states (tiny: live in L2)
__device__ float    g_h1[2 * NGROUPS * BG * 256];
__device__ float    g_h2[2 * NGROUPS * BG * 256];
__device__ unsigned g_flags[NCTA];

__global__ void init_kernel() {
    if (threadIdx.x < NCTA) g_flags[threadIdx.x] = 0u;
}

__device__ __forceinline__ float sigmoidf_(float x) {
    return __fdividef(1.0f, 1.0f + __expf(-x));
}

// packed f32x2 fma
__device__ __forceinline__ u64 ffma2(u64 a, u64 b, u64 c) {
    u64 d;
    asm("fma.rn.f32x2 %0, %1, %2, %3;" : "=l"(d) : "l"(a), "l"(b), "l"(c));
    return d;
}

// arrive: block sync, then tid0 fences + publishes epoch to this CTA's flag
__device__ __forceinline__ void bar_arrive(unsigned cta, unsigned e) {
    __syncthreads();
    if (threadIdx.x == 0) {
        __threadfence();
        atomicExch(&g_flags[cta], e);
    }
}
// wait: warp 0 polls all 16 flags of the group (one 64B sector), broadcast via bar
__device__ __forceinline__ void bar_wait(int grp, unsigned e) {
    if (threadIdx.x < 32) {
        int lane = threadIdx.x;
        for (;;) {
            unsigned v = e;
            if (lane < 16) v = ((volatile unsigned*)g_flags)[grp * 16 + lane];
            if (__all_sync(0xffffffffu, v >= e)) break;
        }
        if (lane == 0) __threadfence();
    }
    __syncthreads();
}

__global__ void __launch_bounds__(NT, 1)
gru_kernel(const float* __restrict__ inp, const float* __restrict__ W1,
           const float* __restrict__ U1g, const float* __restrict__ b1,
           const float* __restrict__ W2g, const float* __restrict__ U2g,
           const float* __restrict__ b2, float* __restrict__ out)
{
    extern __shared__ float smem[];
    float* sW    = smem;                  // [144][WS]: 0..47 U1, 48..95 W2, 96..143 U2 (transposed)
    float* sh1   = sW    + 144 * WS;      // [8][SPH]  h1[i-1]
    float* sh2   = sh1   +   8 * SPH;     // [8][SPH]  h2[i-2]
    float* sW1t  = sh2   +   8 * SPH;     // [48][16]
    float* sx    = sW1t  +  48 * 16;      // [8][16]
    float* sb    = sx    +   8 * 16;      // [4*48]: b1_in | b1_rec | b2_in | b2_rec
    float* red   = sb    +   4 * 48;      // [8 kc][8 rows * RB]

    const int tid   = threadIdx.x;
    const int cta   = blockIdx.x;
    const int grp   = cta >> 4;
    const int sl    = cta & 15;
    const int brow0 = grp * BG;

    // ---- one-time: load weight slices (transposed) into SMEM ----
    for (int idx = tid; idx < 48 * 256; idx += NT) {
        int k = idx / 48, c = idx - k * 48;
        int col = ((c >> 4) << 8) + (sl << 4) + (c & 15);   // gate*256 + slice*16 + u
        sW[c * WS + k]          = U1g[k * 768 + col];
        sW[(48 + c) * WS + k]   = W2g[k * 768 + col];
        sW[(96 + c) * WS + k]   = U2g[k * 768 + col];
    }
    for (int idx = tid; idx < 48 * 15; idx += NT) {
        int f = idx / 48, c = idx - f * 48;
        int col = ((c >> 4) << 8) + (sl << 4) + (c & 15);
        sW1t[c * 16 + f] = W1[f * 768 + col];
    }
    for (int c = tid; c < 48; c += NT) {
        int col = ((c >> 4) << 8) + (sl << 4) + (c & 15);
        sb[c]        = b1[col];        // b1_in
        sb[48 + c]   = b1[768 + col];  // b1_rec
        sb[96 + c]   = b2[col];        // b2_in
        sb[144 + c]  = b2[768 + col];  // b2_rec
    }
    if (tid < 128) {
        int b = tid & 7, u = tid >> 3;
        int scol = (sl << 4) + u;
        for (int buf = 0; buf < 2; buf++) {
            g_h1[(buf * NGROUPS + grp) * BG * 256 + b * 256 + scol] = 0.f;
            g_h2[(buf * NGROUPS + grp) * BG * 256 + b * 256 + scol] = 0.f;
        }
    }

    // GEMM decomposition (all 384 threads): kc (k-chunk of 32) x cg (6 cols) x rh (4 rows)
    const int kc  = tid / 48;          // 0..7
    const int r48 = tid - kc * 48;
    const int cg  = r48 >> 1;          // 0..23 (cols cg*6..cg*6+5; cg<16 -> h1, else h2)
    const int rh  = r48 & 1;           // 0..1
    const float* hsel = (cg < 16 ? sh1 : sh2) + rh * 4 * SPH + kc * 32;
    const float* wbse = sW + (cg * 6) * WS + kc * 32;

    const int b15 = tid / 15, f15 = tid - b15 * 15;   // input-load map (tid<120)

    // register-resident own state element
    float hp1 = 0.f;   // valid for tid < 128
    float hp2 = 0.f;   // valid for 128 <= tid < 256

    bar_arrive(cta, 1u);
    bar_wait(grp, 1u);

    for (int i = 0; i <= TSTEPS; ++i) {
        // ---- prefetch input row i (independent of barrier) ----
        float xin = 0.f;
        if (i < TSTEPS && tid < 120)
            xin = __ldg(&inp[(size_t)(brow0 + b15) * (TSTEPS * FDIM) + i * FDIM + f15]);

        if (i > 0) bar_wait(grp, (unsigned)(i + 1));

        // ---- phase 1: load shared state (L2-coherent) ----
        {
            const float* gh1 = g_h1 + (((i + 1) & 1) * NGROUPS + grp) * BG * 256;  // h1[i-1]
            const float* gh2 = g_h2 + (((i) & 1)     * NGROUPS + grp) * BG * 256;  // h2[i-2]
            for (int idx = tid; idx < 512; idx += NT) {
                int b = idx >> 6, k4 = idx & 63;
                float4 v1 = __ldcg(((const float4*)(gh1 + b * 256)) + k4);
                float4 v2 = __ldcg(((const float4*)(gh2 + b * 256)) + k4);
                *(float4*)(sh1 + b * SPH + (k4 << 2)) = v1;
                *(float4*)(sh2 + b * SPH + (k4 << 2)) = v2;
            }
            if (i < TSTEPS && tid < 120) sx[b15 * 16 + f15] = xin;
        }
        __syncthreads();

        // ---- phase 2: fused register-tiled GEMM (384 threads, 4x6 tile) ----
        {
            u64 acc[4][6];
            #pragma unroll
            for (int j = 0; j < 4; j++)
                #pragma unroll
                for (int jj = 0; jj < 6; jj++) acc[j][jj] = 0ull;

            #pragma unroll
            for (int s = 0; s < 8; s++) {
                ulonglong2 h2v[4];
                #pragma unroll
                for (int j = 0; j < 4; j++)
                    h2v[j] = *(const ulonglong2*)(hsel + j * SPH + s * 4);
                #pragma unroll
                for (int jj = 0; jj < 6; jj++) {
                    ulonglong2 w2 = *(const ulonglong2*)(wbse + jj * WS + s * 4);
                    #pragma unroll
                    for (int j = 0; j < 4; j++) {
                        acc[j][jj] = ffma2(h2v[j].x, w2.x, acc[j][jj]);
                        acc[j][jj] = ffma2(h2v[j].y, w2.y, acc[j][jj]);
                    }
                }
            }
            #pragma unroll
            for (int j = 0; j < 4; j++) {
                int row = rh * 4 + j;
                #pragma unroll
                for (int jj = 0; jj < 6; jj += 2) {
                    float2 p0 = *(float2*)&acc[j][jj];
                    float2 p1 = *(float2*)&acc[j][jj + 1];
                    *(float2*)&red[kc * RKC + row * RB + cg * 6 + jj] =
                        make_float2(p0.x + p0.y, p1.x + p1.y);
                }
            }
        }
        __syncthreads();

        // ---- phase 3: parallel gates with fused k-reduce ----
        if (tid < 128) {
            // layer 1: h1[i]
            if (i < TSTEPS) {
                int b = tid & 7, u = tid >> 3;
                int scol = (sl << 4) + u;
                const float* rrow = red + b * RB;
                float rec[3], xp[3];
                #pragma unroll
                for (int g = 0; g < 3; g++) {
                    int c = g * 16 + u;
                    float s = rrow[c];
                    #pragma unroll
                    for (int k2 = 1; k2 < 8; k2++) s += rrow[k2 * RKC + c];
                    rec[g] = s + sb[48 + c];                 // + b1_rec
                    float a = sb[c];                         // b1_in
                    const float* wr = sW1t + c * 16;
                    const float* xr = sx + b * 16;
                    #pragma unroll
                    for (int f = 0; f < 15; f++) a += xr[f] * wr[f];
                    xp[g] = a;
                }
                float z  = sigmoidf_(xp[0] + rec[0]);
                float r  = sigmoidf_(xp[1] + rec[1]);
                float hh = fmaxf(0.f, xp[2] + r * rec[2]);
                float hn = z * hp1 + (1.f - z) * hh;
                hp1 = hn;
                g_h1[((i & 1) * NGROUPS + grp) * BG * 256 + b * 256 + scol] = hn;
                if (i == TSTEPS - 1) out[64 * 256 + (brow0 + b) * 256 + scol] = hn;  // state1
            }
        } else if (tid < 256) {
            // layer 2: h2[i-1]
            if (i >= 1) {
                int bu = tid - 128;
                int b = bu & 7, u = bu >> 3;
                int scol = (sl << 4) + u;
                int gb = brow0 + b;
                const float* rrow = red + b * RB;
                float xpv[3], rec[3];
                #pragma unroll
                for (int g = 0; g < 3; g++) {
                    int cx = 48 + g * 16 + u;
                    int cr = 96 + g * 16 + u;
                    float sx_ = rrow[cx];
                    float sr_ = rrow[cr];
                    #pragma unroll
                    for (int k2 = 1; k2 < 8; k2++) {
                        sx_ += rrow[k2 * RKC + cx];
                        sr_ += rrow[k2 * RKC + cr];
                    }
                    xpv[g] = sx_ + sb[96 + g * 16 + u];   // + b2_in
                    rec[g] = sr_ + sb[144 + g * 16 + u];  // + b2_rec
                }
                float z  = sigmoidf_(xpv[0] + rec[0]);
                float r  = sigmoidf_(xpv[1] + rec[1]);
                float hh = fmaxf(0.f, xpv[2] + r * rec[2]);
                float hn = z * hp2 + (1.f - z) * hh;
                hp2 = hn;
                g_h2[(((i - 1) & 1) * NGROUPS + grp) * BG * 256 + b * 256 + scol] = hn;
                if (i == TSTEPS) {
                    out[gb * 256 + scol]                = hn;   // x = seq2[:, -1, :]
                    out[2 * 64 * 256 + gb * 256 + scol] = hn;   // state2
                }
            }
        }

        bar_arrive(cta, (unsigned)(i + 2));
    }
}

extern "C" void kernel_launch(void* const* d_in, const int* in_sizes, int n_in,
                              void* d_out, int out_size) {
    const float* inp = (const float*)d_in[0];
    const float* W1  = (const float*)d_in[1];
    const float* U1  = (const float*)d_in[2];
    const float* b1  = (const float*)d_in[3];
    const float* W2  = (const float*)d_in[4];
    const float* U2  = (const float*)d_in[5];
    const float* b2  = (const float*)d_in[6];
    float* out = (float*)d_out;

    size_t smem_bytes = (size_t)(144 * WS + 2 * 8 * SPH +
                                 48 * 16 + 8 * 16 + 4 * 48 +
                                 8 * RKC) * sizeof(float);
    cudaFuncSetAttribute(gru_kernel, cudaFuncAttributeMaxDynamicSharedMemorySize,
                         (int)smem_bytes);
    init_kernel<<<1, 128>>>();
    gru_kernel<<<NCTA, NT, smem_bytes>>>(inp, W1, U1, b1, W2, U2, b2, out);
}